// round 12
// baseline (speedup 1.0000x reference)
#include <cuda_runtime.h>
#include <cuda_fp16.h>
#include <cstdint>
#include <cstddef>

#define Bb   16
#define Cc   128
#define Hh   64
#define Ww   64
#define NHh  8
#define HDd  16
#define HW   4096
#define OUTC 512

// ---------------------------------------------------------------------------
// Scratch
// ---------------------------------------------------------------------------
__device__ __half g_s[Bb * Cc * HW];
__device__ __half g_srch[Bb * Cc * HW];
__device__ __half g_qkv[Bb * 3 * Cc * HW];
__device__ float  g_lampart[8 * 128 * 16 * 17];  // [slice][bh][i][o(16)+se]
__device__ float  g_lambda[Bb * NHh * HDd * HDd];
__device__ float  g_poolpart[Bb * Cc * 4];
__device__ __half g_w2b[Bb * OUTC * Cc];
__device__ __half g_r1[Bb * Cc * HW];
__device__ __half g_wq[3 * Cc * Cc];
__device__ __half g_w1[OUTC * Cc];

// ---------------------------------------------------------------------------
// helpers
// ---------------------------------------------------------------------------
__device__ __forceinline__ void mma_f16(float* c, const uint32_t* a, const uint32_t* b) {
    asm volatile(
        "mma.sync.aligned.m16n8k16.row.col.f32.f16.f16.f32 "
        "{%0,%1,%2,%3}, {%4,%5,%6,%7}, {%8,%9}, {%0,%1,%2,%3};\n"
        : "+f"(c[0]), "+f"(c[1]), "+f"(c[2]), "+f"(c[3])
        : "r"(a[0]), "r"(a[1]), "r"(a[2]), "r"(a[3]), "r"(b[0]), "r"(b[1]));
}

__device__ __forceinline__ void ldsm_x4(uint32_t* r, uint32_t addr) {
    asm volatile("ldmatrix.sync.aligned.m8n8.x4.shared.b16 {%0,%1,%2,%3}, [%4];"
                 : "=r"(r[0]), "=r"(r[1]), "=r"(r[2]), "=r"(r[3]) : "r"(addr));
}
__device__ __forceinline__ void ldsm_x2t(uint32_t* r, uint32_t addr) {
    asm volatile("ldmatrix.sync.aligned.m8n8.x2.trans.shared.b16 {%0,%1}, [%2];"
                 : "=r"(r[0]), "=r"(r[1]) : "r"(addr));
}

__device__ __forceinline__ void cp16(uint32_t smem, const void* gptr) {
    asm volatile("cp.async.cg.shared.global [%0], [%1], 16;\n" :: "r"(smem), "l"(gptr));
}
__device__ __forceinline__ void cp_commit() {
    asm volatile("cp.async.commit_group;\n");
}
template <int N>
__device__ __forceinline__ void cp_wait() {
    asm volatile("cp.async.wait_group %0;\n" :: "n"(N));
}

__device__ __forceinline__ void store2(__half* p, float a, float b) {
    *reinterpret_cast<__half2*>(p) = __floats2half2_rn(a, b);
}
__device__ __forceinline__ void store2(float* p, float a, float b) {
    *reinterpret_cast<float2*>(p) = make_float2(a, b);
}

// ---------------------------------------------------------------------------
// 1) CPE (half out) + src half copy + pool quarter-partials
// ---------------------------------------------------------------------------
__global__ __launch_bounds__(256) void k_cpe(const float* __restrict__ src,
                                             const float* __restrict__ cpe_w,
                                             __half* __restrict__ s,
                                             __half* __restrict__ srch,
                                             float* __restrict__ poolpart) {
    int gid = blockIdx.x * 256 + threadIdx.x;
    int p4 = gid * 4;
    int x = p4 & 63;
    int h = (p4 >> 6) & 63;
    int c = (p4 >> 12) & 127;
    const float* wp = cpe_w + c * 9;

    float a0 = 0.f, a1 = 0.f, a2 = 0.f, a3 = 0.f;
    float4 ctr = *reinterpret_cast<const float4*>(src + p4);

#pragma unroll
    for (int dy = -1; dy <= 1; dy++) {
        int hy = h + dy;
        if (hy < 0 || hy >= Hh) continue;
        const float* r = src + p4 + dy * Ww;
        float4 m = (dy == 0) ? ctr : *reinterpret_cast<const float4*>(r);
        float lft = (x > 0)  ? r[-1] : 0.f;
        float rgt = (x < 60) ? r[4]  : 0.f;
        float wl = wp[(dy + 1) * 3 + 0];
        float wc = wp[(dy + 1) * 3 + 1];
        float wr = wp[(dy + 1) * 3 + 2];
        a0 += wl * lft + wc * m.x + wr * m.y;
        a1 += wl * m.x + wc * m.y + wr * m.z;
        a2 += wl * m.y + wc * m.z + wr * m.w;
        a3 += wl * m.z + wc * m.w + wr * rgt;
    }
    __half2* sp = reinterpret_cast<__half2*>(s + p4);
    sp[0] = __floats2half2_rn(a0 + ctr.x, a1 + ctr.y);
    sp[1] = __floats2half2_rn(a2 + ctr.z, a3 + ctr.w);
    __half2* cph = reinterpret_cast<__half2*>(srch + p4);
    cph[0] = __floats2half2_rn(ctr.x, ctr.y);
    cph[1] = __floats2half2_rn(ctr.z, ctr.w);

    float psum = ctr.x + ctr.y + ctr.z + ctr.w;
    __shared__ float sm[256];
    sm[threadIdx.x] = psum;
    __syncthreads();
    for (int sstep = 128; sstep > 0; sstep >>= 1) {
        if (threadIdx.x < sstep) sm[threadIdx.x] += sm[threadIdx.x + sstep];
        __syncthreads();
    }
    if (threadIdx.x == 0) poolpart[blockIdx.x] = sm[0];
}

// ---------------------------------------------------------------------------
// 2) fused wconv + ECA + w2b
// ---------------------------------------------------------------------------
__device__ __forceinline__ float poolsum(const float* pp, int pc) {
    return pp[pc * 4] + pp[pc * 4 + 1] + pp[pc * 4 + 2] + pp[pc * 4 + 3];
}

__global__ __launch_bounds__(256) void k_w2b(const float* __restrict__ qkv_w,
                                             const float* __restrict__ out_w,
                                             const float* __restrict__ poolpart,
                                             const float* __restrict__ conv1d_w,
                                             __half* __restrict__ wq,
                                             __half* __restrict__ w1,
                                             __half* __restrict__ w2b) {
    int idx = blockIdx.x * 256 + threadIdx.x;
    if (idx >= Bb * OUTC * Cc) return;
    if (idx < 3 * Cc * Cc) wq[idx] = __float2half_rn(qkv_w[idx]);
    if (idx < OUTC * Cc) {
        int o = idx >> 7, c2 = idx & 127;
        w1[idx] = __float2half_rn(out_w[o * 256 + c2]);
    }
    int c = idx & 127;
    int o = (idx >> 7) & 511;
    int b = idx >> 16;
    int pc = (b << 7) + c;
    const float inv = 1.0f / HW;
    float left  = (c > 0)   ? poolsum(poolpart, pc - 1) * inv : 0.f;
    float mid   = poolsum(poolpart, pc) * inv;
    float right = (c < 127) ? poolsum(poolpart, pc + 1) * inv : 0.f;
    float z = conv1d_w[0] * left + conv1d_w[1] * mid + conv1d_w[2] * right;
    float ca = 1.0f / (1.0f + __expf(-z));
    w2b[idx] = __float2half_rn(out_w[o * 256 + 128 + c] * ca);
}

// ---------------------------------------------------------------------------
// 3) fp16 GEMM (unchanged)
// ---------------------------------------------------------------------------
template <int NPARTS, typename OutT>
__global__ __launch_bounds__(256, 2) void k_mma_gemm(
    const __half* __restrict__ A0, size_t sA0,
    const __half* __restrict__ B0, size_t sB0,
    const __half* __restrict__ A1, size_t sA1,
    const __half* __restrict__ B1, size_t sB1,
    OutT* __restrict__ C, size_t sC) {
    constexpr int BlkM = 128, BlkN = 128, BlkK = 16;
    constexpr int ASTh = 24;
    constexpr int BSTh = 136;
    constexpr int ASZh = BlkM * ASTh;
    constexpr int BSZh = BlkK * BSTh;

    extern __shared__ __half smh[];
    __half* Asm = smh;
    __half* Bsm = smh + 3 * ASZh;
    const uint32_t a_base0 = (uint32_t)__cvta_generic_to_shared(Asm);
    const uint32_t b_base0 = (uint32_t)__cvta_generic_to_shared(Bsm);

    const int tid = threadIdx.x;
    const int bz = blockIdx.z, mtile = blockIdx.x, ntile = blockIdx.y;
    const int warp = tid >> 5, lane = tid & 31;
    const int g = lane >> 2, t = lane & 3;
    const int wm = (warp >> 2) * 64;
    const int wn = (warp & 3) * 32;

    auto load_chunk = [&](int cidx, int buf) {
        const int part = (NPARTS == 2) ? (cidx >> 3) : 0;
        const int kin = (cidx & 7) * BlkK;
        const __half* Aptr = part ? A1 + (size_t)bz * sA1 : A0 + (size_t)bz * sA0;
        const __half* Bptr = part ? B1 + (size_t)bz * sB1 : B0 + (size_t)bz * sB0;
        __half* Abuf = Asm + buf * ASZh;
        __half* Bbuf = Bsm + buf * BSZh;
        {
            int row = tid >> 1, ho = (tid & 1) * 8;
            cp16((uint32_t)__cvta_generic_to_shared(&Abuf[row * ASTh + ho]),
                 Aptr + (size_t)(mtile * BlkM + row) * 128 + kin + ho);
        }
        {
            int kk = tid >> 4, col = (tid & 15) * 8;
            cp16((uint32_t)__cvta_generic_to_shared(&Bbuf[kk * BSTh + col]),
                 Bptr + (size_t)(kin + kk) * HW + ntile * BlkN + col);
        }
        cp_commit();
    };

    float acc[4][4][4];
#pragma unroll
    for (int f = 0; f < 4; f++)
#pragma unroll
        for (int nf = 0; nf < 4; nf++)
#pragma unroll
            for (int j = 0; j < 4; j++) acc[f][nf][j] = 0.f;

    const int a_row_in = (lane & 7) + ((lane >> 3) & 1) * 8;
    const int a_kbase  = (lane >> 4) * 8;
    const int b_krow   = lane & 15;

    auto compute = [&](int buf) {
        const uint32_t a_base = a_base0 + buf * ASZh * 2;
        const uint32_t b_base = b_base0 + buf * BSZh * 2;
        uint32_t areg[4][4];
#pragma unroll
        for (int f = 0; f < 4; f++) {
            uint32_t addr = a_base +
                (uint32_t)(((wm + f * 16 + a_row_in) * ASTh + a_kbase) * 2);
            ldsm_x4(areg[f], addr);
        }
        uint32_t breg[4][2];
#pragma unroll
        for (int nf = 0; nf < 4; nf++) {
            uint32_t addr = b_base +
                (uint32_t)((b_krow * BSTh + wn + nf * 8) * 2);
            ldsm_x2t(breg[nf], addr);
        }
#pragma unroll
        for (int f = 0; f < 4; f++)
#pragma unroll
            for (int nf = 0; nf < 4; nf++)
                mma_f16(acc[f][nf], areg[f], breg[nf]);
    };

    const int NC = NPARTS * 8;
    load_chunk(0, 0);
    load_chunk(1, 1);
    for (int cidx = 0; cidx < NC; cidx++) {
        if (cidx < NC - 1) cp_wait<1>(); else cp_wait<0>();
        __syncthreads();
        if (cidx + 2 < NC) load_chunk(cidx + 2, (cidx + 2) % 3);
        compute(cidx % 3);
    }

    OutT* Cbase = C + (size_t)bz * sC + (size_t)(mtile * BlkM) * HW + ntile * BlkN;
#pragma unroll
    for (int f = 0; f < 4; f++) {
#pragma unroll
        for (int nf = 0; nf < 4; nf++) {
            int row = wm + f * 16 + g;
            int col = wn + nf * 8 + t * 2;
            store2(Cbase + (size_t)row * HW + col, acc[f][nf][0], acc[f][nf][1]);
            store2(Cbase + (size_t)(row + 8) * HW + col, acc[f][nf][2], acc[f][nf][3]);
        }
    }
}

// ---------------------------------------------------------------------------
// 4) softmax partials: grid (bh=128, slice=8). Vectorized: uint2 k loads
//    (4 halves) + float4 v smem loads. Writes [Σ e·v (16), Σ e] per (bh,i,slice).
// ---------------------------------------------------------------------------
__global__ __launch_bounds__(256) void k_softmax_part(const __half* __restrict__ qkv,
                                                      float* __restrict__ lampart) {
    const int bh = blockIdx.x;
    const int slice = blockIdx.y;
    const int n0 = slice * 512;
    const int b = bh >> 3, nh = bh & 7;
    const __half* kbase = qkv + ((size_t)b * 384 + 128 + nh * 16) * HW;
    const __half* vbase = qkv + ((size_t)b * 384 + 256 + nh * 16) * HW;
    const int tid = threadIdx.x;
    const int warp = tid >> 5, lane = tid & 31;
    const int i0 = warp * 2;

    __shared__ float vsm[16][512];
    for (int t2 = tid; t2 < 16 * 256; t2 += 256) {
        int o = t2 >> 8, n2 = (t2 & 255) * 2;
        __half2 hv = *reinterpret_cast<const __half2*>(vbase + (size_t)o * HW + n0 + n2);
        vsm[o][n2]     = __low2float(hv);
        vsm[o][n2 + 1] = __high2float(hv);
    }
    __syncthreads();

    const __half* k0 = kbase + (size_t)(i0 + 0) * HW + n0;
    const __half* k1 = kbase + (size_t)(i0 + 1) * HW + n0;
    float acc0[16], acc1[16];
#pragma unroll
    for (int o = 0; o < 16; o++) { acc0[o] = 0.f; acc1[o] = 0.f; }
    float se0 = 0.f, se1 = 0.f;

#pragma unroll
    for (int it = 0; it < 4; it++) {
        int n = lane * 4 + it * 128;
        uint2 kr0 = *reinterpret_cast<const uint2*>(k0 + n);
        uint2 kr1 = *reinterpret_cast<const uint2*>(k1 + n);
        __half2 h0a = *reinterpret_cast<__half2*>(&kr0.x);
        __half2 h0b = *reinterpret_cast<__half2*>(&kr0.y);
        __half2 h1a = *reinterpret_cast<__half2*>(&kr1.x);
        __half2 h1b = *reinterpret_cast<__half2*>(&kr1.y);
        float e00 = __expf(__low2float(h0a)), e01 = __expf(__high2float(h0a));
        float e02 = __expf(__low2float(h0b)), e03 = __expf(__high2float(h0b));
        float e10 = __expf(__low2float(h1a)), e11 = __expf(__high2float(h1a));
        float e12 = __expf(__low2float(h1b)), e13 = __expf(__high2float(h1b));
        se0 += e00 + e01 + e02 + e03;
        se1 += e10 + e11 + e12 + e13;
#pragma unroll
        for (int o = 0; o < 16; o++) {
            float4 v = *reinterpret_cast<const float4*>(&vsm[o][n]);
            acc0[o] += e00 * v.x + e01 * v.y + e02 * v.z + e03 * v.w;
            acc1[o] += e10 * v.x + e11 * v.y + e12 * v.z + e13 * v.w;
        }
    }

#pragma unroll
    for (int off = 16; off > 0; off >>= 1) {
        se0 += __shfl_xor_sync(0xffffffff, se0, off);
        se1 += __shfl_xor_sync(0xffffffff, se1, off);
#pragma unroll
        for (int o = 0; o < 16; o++) {
            acc0[o] += __shfl_xor_sync(0xffffffff, acc0[o], off);
            acc1[o] += __shfl_xor_sync(0xffffffff, acc1[o], off);
        }
    }
    if (lane == 0) {
        float* P0 = lampart + (((size_t)slice * 128 + bh) * 16 + i0) * 17;
#pragma unroll
        for (int o = 0; o < 16; o++) P0[o] = acc0[o];
        P0[16] = se0;
        float* P1 = P0 + 17;
#pragma unroll
        for (int o = 0; o < 16; o++) P1[o] = acc1[o];
        P1[16] = se1;
    }
}

// ---------------------------------------------------------------------------
// 5) lambda finalize: reduce 8 slices, normalize, scale. grid 128 x 256t.
// ---------------------------------------------------------------------------
__global__ __launch_bounds__(256) void k_lam_fin(const float* __restrict__ lampart,
                                                 float* __restrict__ lambda) {
    const int bh = blockIdx.x;
    const int tid = threadIdx.x;
    const int i = tid >> 4, o = tid & 15;
    float a = 0.f, s = 0.f;
#pragma unroll
    for (int sl = 0; sl < 8; sl++) {
        const float* P = lampart + (((size_t)sl * 128 + bh) * 16 + i) * 17;
        a += P[o];
        s += P[16];
    }
    lambda[(size_t)bh * 256 + i * 16 + o] = 0.25f * a / s;
}

// ---------------------------------------------------------------------------
// 6) result1 = content + q * position_lambda (EXACT R10 version)
// ---------------------------------------------------------------------------
__global__ __launch_bounds__(256) void k_result1(const __half* __restrict__ qkv,
                                                 const float* __restrict__ lambda,
                                                 const float* __restrict__ rel_pos,
                                                 __half* __restrict__ r1) {
    const int bh = blockIdx.z;
    const int b = bh >> 3, nh = bh & 7;
    const int x0 = blockIdx.x * 16, y0 = blockIdx.y * 16;
    const int tid = threadIdx.x;
    const int px = tid & 15, py = tid >> 4;

    __shared__ float lam[16][16];
    __shared__ float relw[16][25];
    __shared__ float qs[16][16][16];
    __shared__ float vs[16][20][20];

    lam[py][px] = lambda[((size_t)bh * 16 + py) * 16 + px];
    for (int t = tid; t < 400; t += 256) relw[t / 25][t % 25] = rel_pos[t];
    const __half* qbase = qkv + ((size_t)b * 384 + nh * 16) * HW;
#pragma unroll
    for (int ch = 0; ch < 16; ch++)
        qs[ch][py][px] = __half2float(qbase[(size_t)ch * HW + (y0 + py) * Ww + x0 + px]);
    const __half* vbase = qkv + ((size_t)b * 384 + 256 + nh * 16) * HW;
    for (int t = tid; t < 6400; t += 256) {
        int ch = t / 400;
        int r = t % 400;
        int vy = r / 20, vx = r % 20;
        int gy = y0 + vy - 2, gx = x0 + vx - 2;
        float val = 0.f;
        if (gy >= 0 && gy < Hh && gx >= 0 && gx < Ww)
            val = __half2float(vbase[(size_t)ch * HW + gy * Ww + gx]);
        vs[ch][vy][vx] = val;
    }
    __syncthreads();

    __half* obase = r1 + ((size_t)b * Cc + nh * 16) * HW + (y0 + py) * Ww + x0 + px;
#pragma unroll
    for (int o = 0; o < 16; o++) {
        float content = 0.f;
#pragma unroll
        for (int i = 0; i < 16; i++) content += qs[i][py][px] * lam[i][o];
        float pos = 0.f;
#pragma unroll
        for (int ky = 0; ky < 5; ky++)
#pragma unroll
            for (int kx = 0; kx < 5; kx++)
                pos += relw[o][ky * 5 + kx] * vs[o][py + ky][px + kx];
        obase[(size_t)o * HW] = __float2half_rn(content + qs[o][py][px] * pos);
    }
}

// ---------------------------------------------------------------------------
// Launch
// ---------------------------------------------------------------------------
extern "C" void kernel_launch(void* const* d_in, const int* in_sizes, int n_in,
                              void* d_out, int out_size) {
    const float* src      = (const float*)d_in[0];
    const float* cpe_w    = (const float*)d_in[1];
    const float* qkv_w    = (const float*)d_in[2];
    const float* rel_pos  = (const float*)d_in[3];
    const float* conv1d_w = (const float*)d_in[4];
    const float* out_w    = (const float*)d_in[5];
    float* out = (float*)d_out;

    __half *s_p, *srch_p, *qkv_p, *w2b_p, *r1_p, *wq_p, *w1_p;
    float *lamp_p, *lam_p, *pp_p;
    cudaGetSymbolAddress((void**)&s_p,    g_s);
    cudaGetSymbolAddress((void**)&srch_p, g_srch);
    cudaGetSymbolAddress((void**)&qkv_p,  g_qkv);
    cudaGetSymbolAddress((void**)&lamp_p, g_lampart);
    cudaGetSymbolAddress((void**)&lam_p,  g_lambda);
    cudaGetSymbolAddress((void**)&pp_p,   g_poolpart);
    cudaGetSymbolAddress((void**)&w2b_p,  g_w2b);
    cudaGetSymbolAddress((void**)&r1_p,   g_r1);
    cudaGetSymbolAddress((void**)&wq_p,   g_wq);
    cudaGetSymbolAddress((void**)&w1_p,   g_w1);

    const int gemm_smem = 3 * (128 * 24 + 16 * 136) * 2;  // 31488 bytes
    cudaFuncSetAttribute(k_mma_gemm<1, __half>, cudaFuncAttributeMaxDynamicSharedMemorySize, gemm_smem);
    cudaFuncSetAttribute(k_mma_gemm<2, float>,  cudaFuncAttributeMaxDynamicSharedMemorySize, gemm_smem);

    k_cpe<<<Bb * Cc * HW / 1024, 256>>>(src, cpe_w, s_p, srch_p, pp_p);
    k_w2b<<<(Bb * OUTC * Cc + 255) / 256, 256>>>(qkv_w, out_w, pp_p, conv1d_w,
                                                 wq_p, w1_p, w2b_p);
    {
        dim3 grid(3 * Cc / 128, HW / 128, Bb);
        k_mma_gemm<1, __half><<<grid, 256, gemm_smem>>>(wq_p, 0,
                                                        s_p, (size_t)Cc * HW,
                                                        nullptr, 0, nullptr, 0,
                                                        qkv_p, (size_t)3 * Cc * HW);
    }
    {
        dim3 grid(Bb * NHh, 8);
        k_softmax_part<<<grid, 256>>>(qkv_p, lamp_p);
    }
    k_lam_fin<<<Bb * NHh, 256>>>(lamp_p, lam_p);
    {
        dim3 grid(Ww / 16, Hh / 16, Bb * NHh);
        k_result1<<<grid, 256>>>(qkv_p, lam_p, rel_pos, r1_p);
    }
    {
        dim3 grid(OUTC / 128, HW / 128, Bb);
        k_mma_gemm<2, float><<<grid, 256, gemm_smem>>>(w1_p, 0,
                                                       r1_p, (size_t)Cc * HW,
                                                       w2b_p, (size_t)OUTC * Cc,
                                                       srch_p, (size_t)Cc * HW,
                                                       out, (size_t)OUTC * HW);
    }
}

// round 13
// speedup vs baseline: 1.4977x; 1.4977x over previous
#include <cuda_runtime.h>
#include <cuda_fp16.h>
#include <cstdint>
#include <cstddef>

#define Bb   16
#define Cc   128
#define Hh   64
#define Ww   64
#define NHh  8
#define HDd  16
#define HW   4096
#define OUTC 512

// ---------------------------------------------------------------------------
// Scratch
// ---------------------------------------------------------------------------
__device__ __half g_s[Bb * Cc * HW];          // CPE out, half
__device__ __half g_srch[Bb * Cc * HW];       // src, half
__device__ __half g_qkv[Bb * 3 * Cc * HW];    // qkv, half
__device__ float  g_lambda[Bb * NHh * HDd * HDd];
__device__ float  g_poolpart[Bb * Cc * 4];    // per-quarter partial sums
__device__ __half g_w2b[Bb * OUTC * Cc];      // half, lda=128
__device__ __half g_r1[Bb * Cc * HW];         // half
__device__ __half g_wq[3 * Cc * Cc];          // qkv_w half, lda=128
__device__ __half g_w1[OUTC * Cc];            // out_w[:, :128] half, lda=128

// ---------------------------------------------------------------------------
// helpers
// ---------------------------------------------------------------------------
__device__ __forceinline__ void mma_f16(float* c, const uint32_t* a, const uint32_t* b) {
    asm volatile(
        "mma.sync.aligned.m16n8k16.row.col.f32.f16.f16.f32 "
        "{%0,%1,%2,%3}, {%4,%5,%6,%7}, {%8,%9}, {%0,%1,%2,%3};\n"
        : "+f"(c[0]), "+f"(c[1]), "+f"(c[2]), "+f"(c[3])
        : "r"(a[0]), "r"(a[1]), "r"(a[2]), "r"(a[3]), "r"(b[0]), "r"(b[1]));
}

__device__ __forceinline__ void ldsm_x4(uint32_t* r, uint32_t addr) {
    asm volatile("ldmatrix.sync.aligned.m8n8.x4.shared.b16 {%0,%1,%2,%3}, [%4];"
                 : "=r"(r[0]), "=r"(r[1]), "=r"(r[2]), "=r"(r[3]) : "r"(addr));
}
__device__ __forceinline__ void ldsm_x2t(uint32_t* r, uint32_t addr) {
    asm volatile("ldmatrix.sync.aligned.m8n8.x2.trans.shared.b16 {%0,%1}, [%2];"
                 : "=r"(r[0]), "=r"(r[1]) : "r"(addr));
}

__device__ __forceinline__ void cp16(uint32_t smem, const void* gptr) {
    asm volatile("cp.async.cg.shared.global [%0], [%1], 16;\n" :: "r"(smem), "l"(gptr));
}
__device__ __forceinline__ void cp_commit() {
    asm volatile("cp.async.commit_group;\n");
}
template <int N>
__device__ __forceinline__ void cp_wait() {
    asm volatile("cp.async.wait_group %0;\n" :: "n"(N));
}

__device__ __forceinline__ void store2(__half* p, float a, float b) {
    *reinterpret_cast<__half2*>(p) = __floats2half2_rn(a, b);
}
__device__ __forceinline__ void store2(float* p, float a, float b) {
    *reinterpret_cast<float2*>(p) = make_float2(a, b);
}

// ---------------------------------------------------------------------------
// 1) CPE (half out) + src half copy + pool quarter-partials (exact R10)
// ---------------------------------------------------------------------------
__global__ __launch_bounds__(256) void k_cpe(const float* __restrict__ src,
                                             const float* __restrict__ cpe_w,
                                             __half* __restrict__ s,
                                             __half* __restrict__ srch,
                                             float* __restrict__ poolpart) {
    int gid = blockIdx.x * 256 + threadIdx.x;
    int p4 = gid * 4;
    int x = p4 & 63;
    int h = (p4 >> 6) & 63;
    int c = (p4 >> 12) & 127;
    const float* wp = cpe_w + c * 9;

    float a0 = 0.f, a1 = 0.f, a2 = 0.f, a3 = 0.f;
    float4 ctr = *reinterpret_cast<const float4*>(src + p4);

#pragma unroll
    for (int dy = -1; dy <= 1; dy++) {
        int hy = h + dy;
        if (hy < 0 || hy >= Hh) continue;
        const float* r = src + p4 + dy * Ww;
        float4 m = (dy == 0) ? ctr : *reinterpret_cast<const float4*>(r);
        float lft = (x > 0)  ? r[-1] : 0.f;
        float rgt = (x < 60) ? r[4]  : 0.f;
        float wl = wp[(dy + 1) * 3 + 0];
        float wc = wp[(dy + 1) * 3 + 1];
        float wr = wp[(dy + 1) * 3 + 2];
        a0 += wl * lft + wc * m.x + wr * m.y;
        a1 += wl * m.x + wc * m.y + wr * m.z;
        a2 += wl * m.y + wc * m.z + wr * m.w;
        a3 += wl * m.z + wc * m.w + wr * rgt;
    }
    __half2* sp = reinterpret_cast<__half2*>(s + p4);
    sp[0] = __floats2half2_rn(a0 + ctr.x, a1 + ctr.y);
    sp[1] = __floats2half2_rn(a2 + ctr.z, a3 + ctr.w);
    __half2* cph = reinterpret_cast<__half2*>(srch + p4);
    cph[0] = __floats2half2_rn(ctr.x, ctr.y);
    cph[1] = __floats2half2_rn(ctr.z, ctr.w);

    float psum = ctr.x + ctr.y + ctr.z + ctr.w;
    __shared__ float sm[256];
    sm[threadIdx.x] = psum;
    __syncthreads();
    for (int sstep = 128; sstep > 0; sstep >>= 1) {
        if (threadIdx.x < sstep) sm[threadIdx.x] += sm[threadIdx.x + sstep];
        __syncthreads();
    }
    if (threadIdx.x == 0) poolpart[blockIdx.x] = sm[0];
}

// ---------------------------------------------------------------------------
// 2) fused wconv + ECA + w2b (exact R10)
// ---------------------------------------------------------------------------
__device__ __forceinline__ float poolsum(const float* pp, int pc) {
    return pp[pc * 4] + pp[pc * 4 + 1] + pp[pc * 4 + 2] + pp[pc * 4 + 3];
}

__global__ __launch_bounds__(256) void k_w2b(const float* __restrict__ qkv_w,
                                             const float* __restrict__ out_w,
                                             const float* __restrict__ poolpart,
                                             const float* __restrict__ conv1d_w,
                                             __half* __restrict__ wq,
                                             __half* __restrict__ w1,
                                             __half* __restrict__ w2b) {
    int idx = blockIdx.x * 256 + threadIdx.x;
    if (idx >= Bb * OUTC * Cc) return;
    if (idx < 3 * Cc * Cc) wq[idx] = __float2half_rn(qkv_w[idx]);
    if (idx < OUTC * Cc) {
        int o = idx >> 7, c2 = idx & 127;
        w1[idx] = __float2half_rn(out_w[o * 256 + c2]);
    }
    int c = idx & 127;
    int o = (idx >> 7) & 511;
    int b = idx >> 16;
    int pc = (b << 7) + c;
    const float inv = 1.0f / HW;
    float left  = (c > 0)   ? poolsum(poolpart, pc - 1) * inv : 0.f;
    float mid   = poolsum(poolpart, pc) * inv;
    float right = (c < 127) ? poolsum(poolpart, pc + 1) * inv : 0.f;
    float z = conv1d_w[0] * left + conv1d_w[1] * mid + conv1d_w[2] * right;
    float ca = 1.0f / (1.0f + __expf(-z));
    w2b[idx] = __float2half_rn(out_w[o * 256 + 128 + c] * ca);
}

// ---------------------------------------------------------------------------
// 3) fp16 GEMM (exact R10)
// ---------------------------------------------------------------------------
template <int NPARTS, typename OutT>
__global__ __launch_bounds__(256, 2) void k_mma_gemm(
    const __half* __restrict__ A0, size_t sA0,
    const __half* __restrict__ B0, size_t sB0,
    const __half* __restrict__ A1, size_t sA1,
    const __half* __restrict__ B1, size_t sB1,
    OutT* __restrict__ C, size_t sC) {
    constexpr int BlkM = 128, BlkN = 128, BlkK = 16;
    constexpr int ASTh = 24;
    constexpr int BSTh = 136;
    constexpr int ASZh = BlkM * ASTh;
    constexpr int BSZh = BlkK * BSTh;

    extern __shared__ __half smh[];
    __half* Asm = smh;
    __half* Bsm = smh + 3 * ASZh;
    const uint32_t a_base0 = (uint32_t)__cvta_generic_to_shared(Asm);
    const uint32_t b_base0 = (uint32_t)__cvta_generic_to_shared(Bsm);

    const int tid = threadIdx.x;
    const int bz = blockIdx.z, mtile = blockIdx.x, ntile = blockIdx.y;
    const int warp = tid >> 5, lane = tid & 31;
    const int g = lane >> 2, t = lane & 3;
    const int wm = (warp >> 2) * 64;
    const int wn = (warp & 3) * 32;

    auto load_chunk = [&](int cidx, int buf) {
        const int part = (NPARTS == 2) ? (cidx >> 3) : 0;
        const int kin = (cidx & 7) * BlkK;
        const __half* Aptr = part ? A1 + (size_t)bz * sA1 : A0 + (size_t)bz * sA0;
        const __half* Bptr = part ? B1 + (size_t)bz * sB1 : B0 + (size_t)bz * sB0;
        __half* Abuf = Asm + buf * ASZh;
        __half* Bbuf = Bsm + buf * BSZh;
        {
            int row = tid >> 1, ho = (tid & 1) * 8;
            cp16((uint32_t)__cvta_generic_to_shared(&Abuf[row * ASTh + ho]),
                 Aptr + (size_t)(mtile * BlkM + row) * 128 + kin + ho);
        }
        {
            int kk = tid >> 4, col = (tid & 15) * 8;
            cp16((uint32_t)__cvta_generic_to_shared(&Bbuf[kk * BSTh + col]),
                 Bptr + (size_t)(kin + kk) * HW + ntile * BlkN + col);
        }
        cp_commit();
    };

    float acc[4][4][4];
#pragma unroll
    for (int f = 0; f < 4; f++)
#pragma unroll
        for (int nf = 0; nf < 4; nf++)
#pragma unroll
            for (int j = 0; j < 4; j++) acc[f][nf][j] = 0.f;

    const int a_row_in = (lane & 7) + ((lane >> 3) & 1) * 8;
    const int a_kbase  = (lane >> 4) * 8;
    const int b_krow   = lane & 15;

    auto compute = [&](int buf) {
        const uint32_t a_base = a_base0 + buf * ASZh * 2;
        const uint32_t b_base = b_base0 + buf * BSZh * 2;
        uint32_t areg[4][4];
#pragma unroll
        for (int f = 0; f < 4; f++) {
            uint32_t addr = a_base +
                (uint32_t)(((wm + f * 16 + a_row_in) * ASTh + a_kbase) * 2);
            ldsm_x4(areg[f], addr);
        }
        uint32_t breg[4][2];
#pragma unroll
        for (int nf = 0; nf < 4; nf++) {
            uint32_t addr = b_base +
                (uint32_t)((b_krow * BSTh + wn + nf * 8) * 2);
            ldsm_x2t(breg[nf], addr);
        }
#pragma unroll
        for (int f = 0; f < 4; f++)
#pragma unroll
            for (int nf = 0; nf < 4; nf++)
                mma_f16(acc[f][nf], areg[f], breg[nf]);
    };

    const int NC = NPARTS * 8;
    load_chunk(0, 0);
    load_chunk(1, 1);
    for (int cidx = 0; cidx < NC; cidx++) {
        if (cidx < NC - 1) cp_wait<1>(); else cp_wait<0>();
        __syncthreads();
        if (cidx + 2 < NC) load_chunk(cidx + 2, (cidx + 2) % 3);
        compute(cidx % 3);
    }

    OutT* Cbase = C + (size_t)bz * sC + (size_t)(mtile * BlkM) * HW + ntile * BlkN;
#pragma unroll
    for (int f = 0; f < 4; f++) {
#pragma unroll
        for (int nf = 0; nf < 4; nf++) {
            int row = wm + f * 16 + g;
            int col = wn + nf * 8 + t * 2;
            store2(Cbase + (size_t)row * HW + col, acc[f][nf][0], acc[f][nf][1]);
            store2(Cbase + (size_t)(row + 8) * HW + col, acc[f][nf][2], acc[f][nf][3]);
        }
    }
}

// ---------------------------------------------------------------------------
// 4) softmax + lambda. grid (bh=128, pair=8), block 128 (4 warps).
//    Each block computes COMPLETE lambda rows for k-rows {2p, 2p+1} over the
//    full spatial range; v staged per 512-chunk as half2 (conflict-free).
//    Writes normalized g_lambda directly — same contract as R10.
// ---------------------------------------------------------------------------
__global__ __launch_bounds__(128) void k_softmax_lambda(const __half* __restrict__ qkv,
                                                        float* __restrict__ lambda) {
    const int bh = blockIdx.x;
    const int pair = blockIdx.y;
    const int i0 = pair * 2;
    const int b = bh >> 3, nh = bh & 7;
    const __half* kbase = qkv + ((size_t)b * 384 + 128 + nh * 16) * HW;
    const __half* vbase = qkv + ((size_t)b * 384 + 256 + nh * 16) * HW;
    const int tid = threadIdx.x;
    const int warp = tid >> 5, lane = tid & 31;

    __shared__ __half2 vsm[16][256];   // 16 KB: 512 n per chunk as half2
    __shared__ float red[4][2][17];    // per-warp partials [warp][row][o|se]

    const __half* k0 = kbase + (size_t)(i0 + 0) * HW;
    const __half* k1 = kbase + (size_t)(i0 + 1) * HW;

    float acc0[16], acc1[16];
#pragma unroll
    for (int o = 0; o < 16; o++) { acc0[o] = 0.f; acc1[o] = 0.f; }
    float se0 = 0.f, se1 = 0.f;

    for (int n0 = 0; n0 < HW; n0 += 512) {
        __syncthreads();
        // stage v chunk: 16 rows x 256 half2; 4096/128 = 32 per thread
        for (int t2 = tid; t2 < 16 * 256; t2 += 128) {
            int o = t2 >> 8, n2 = t2 & 255;
            vsm[o][n2] = *reinterpret_cast<const __half2*>(
                vbase + (size_t)o * HW + n0 + n2 * 2);
        }
        __syncthreads();
        // warps partition the 256 half2 slots: warp w -> [w*64, w*64+64)
#pragma unroll
        for (int it = 0; it < 2; it++) {
            int n2 = warp * 64 + it * 32 + lane;
            __half2 kk0 = *reinterpret_cast<const __half2*>(k0 + n0 + n2 * 2);
            __half2 kk1 = *reinterpret_cast<const __half2*>(k1 + n0 + n2 * 2);
            float e00 = __expf(__low2float(kk0)), e01 = __expf(__high2float(kk0));
            float e10 = __expf(__low2float(kk1)), e11 = __expf(__high2float(kk1));
            se0 += e00 + e01;
            se1 += e10 + e11;
#pragma unroll
            for (int o = 0; o < 16; o++) {
                __half2 hv = vsm[o][n2];
                float vx = __low2float(hv), vy = __high2float(hv);
                acc0[o] += e00 * vx + e01 * vy;
                acc1[o] += e10 * vx + e11 * vy;
            }
        }
    }

    // warp-level reduction
#pragma unroll
    for (int off = 16; off > 0; off >>= 1) {
        se0 += __shfl_xor_sync(0xffffffff, se0, off);
        se1 += __shfl_xor_sync(0xffffffff, se1, off);
#pragma unroll
        for (int o = 0; o < 16; o++) {
            acc0[o] += __shfl_xor_sync(0xffffffff, acc0[o], off);
            acc1[o] += __shfl_xor_sync(0xffffffff, acc1[o], off);
        }
    }
    if (lane < 16) {
        red[warp][0][lane] = acc0[lane];
        red[warp][1][lane] = acc1[lane];
    } else if (lane == 16) {
        red[warp][0][16] = se0;
        red[warp][1][16] = se1;
    }
    __syncthreads();
    if (tid < 32) {
        int r = tid >> 4, o = tid & 15;
        float a = red[0][r][o] + red[1][r][o] + red[2][r][o] + red[3][r][o];
        float s = red[0][r][16] + red[1][r][16] + red[2][r][16] + red[3][r][16];
        lambda[(size_t)bh * 256 + (i0 + r) * 16 + o] = 0.25f * a / s;
    }
}

// ---------------------------------------------------------------------------
// 5) result1 = content + q * position_lambda (exact R10)
// ---------------------------------------------------------------------------
__global__ __launch_bounds__(256) void k_result1(const __half* __restrict__ qkv,
                                                 const float* __restrict__ lambda,
                                                 const float* __restrict__ rel_pos,
                                                 __half* __restrict__ r1) {
    const int bh = blockIdx.z;
    const int b = bh >> 3, nh = bh & 7;
    const int x0 = blockIdx.x * 16, y0 = blockIdx.y * 16;
    const int tid = threadIdx.x;
    const int px = tid & 15, py = tid >> 4;

    __shared__ float lam[16][16];
    __shared__ float relw[16][25];
    __shared__ float qs[16][16][16];
    __shared__ float vs[16][20][20];

    lam[py][px] = lambda[((size_t)bh * 16 + py) * 16 + px];
    for (int t = tid; t < 400; t += 256) relw[t / 25][t % 25] = rel_pos[t];
    const __half* qbase = qkv + ((size_t)b * 384 + nh * 16) * HW;
#pragma unroll
    for (int ch = 0; ch < 16; ch++)
        qs[ch][py][px] = __half2float(qbase[(size_t)ch * HW + (y0 + py) * Ww + x0 + px]);
    const __half* vbase = qkv + ((size_t)b * 384 + 256 + nh * 16) * HW;
    for (int t = tid; t < 6400; t += 256) {
        int ch = t / 400;
        int r = t % 400;
        int vy = r / 20, vx = r % 20;
        int gy = y0 + vy - 2, gx = x0 + vx - 2;
        float val = 0.f;
        if (gy >= 0 && gy < Hh && gx >= 0 && gx < Ww)
            val = __half2float(vbase[(size_t)ch * HW + gy * Ww + gx]);
        vs[ch][vy][vx] = val;
    }
    __syncthreads();

    __half* obase = r1 + ((size_t)b * Cc + nh * 16) * HW + (y0 + py) * Ww + x0 + px;
#pragma unroll
    for (int o = 0; o < 16; o++) {
        float content = 0.f;
#pragma unroll
        for (int i = 0; i < 16; i++) content += qs[i][py][px] * lam[i][o];
        float pos = 0.f;
#pragma unroll
        for (int ky = 0; ky < 5; ky++)
#pragma unroll
            for (int kx = 0; kx < 5; kx++)
                pos += relw[o][ky * 5 + kx] * vs[o][py + ky][px + kx];
        obase[(size_t)o * HW] = __float2half_rn(content + qs[o][py][px] * pos);
    }
}

// ---------------------------------------------------------------------------
// Launch
// ---------------------------------------------------------------------------
extern "C" void kernel_launch(void* const* d_in, const int* in_sizes, int n_in,
                              void* d_out, int out_size) {
    const float* src      = (const float*)d_in[0];
    const float* cpe_w    = (const float*)d_in[1];
    const float* qkv_w    = (const float*)d_in[2];
    const float* rel_pos  = (const float*)d_in[3];
    const float* conv1d_w = (const float*)d_in[4];
    const float* out_w    = (const float*)d_in[5];
    float* out = (float*)d_out;

    __half *s_p, *srch_p, *qkv_p, *w2b_p, *r1_p, *wq_p, *w1_p;
    float *lam_p, *pp_p;
    cudaGetSymbolAddress((void**)&s_p,    g_s);
    cudaGetSymbolAddress((void**)&srch_p, g_srch);
    cudaGetSymbolAddress((void**)&qkv_p,  g_qkv);
    cudaGetSymbolAddress((void**)&lam_p,  g_lambda);
    cudaGetSymbolAddress((void**)&pp_p,   g_poolpart);
    cudaGetSymbolAddress((void**)&w2b_p,  g_w2b);
    cudaGetSymbolAddress((void**)&r1_p,   g_r1);
    cudaGetSymbolAddress((void**)&wq_p,   g_wq);
    cudaGetSymbolAddress((void**)&w1_p,   g_w1);

    const int gemm_smem = 3 * (128 * 24 + 16 * 136) * 2;  // 31488 bytes
    cudaFuncSetAttribute(k_mma_gemm<1, __half>, cudaFuncAttributeMaxDynamicSharedMemorySize, gemm_smem);
    cudaFuncSetAttribute(k_mma_gemm<2, float>,  cudaFuncAttributeMaxDynamicSharedMemorySize, gemm_smem);

    k_cpe<<<Bb * Cc * HW / 1024, 256>>>(src, cpe_w, s_p, srch_p, pp_p);
    k_w2b<<<(Bb * OUTC * Cc + 255) / 256, 256>>>(qkv_w, out_w, pp_p, conv1d_w,
                                                 wq_p, w1_p, w2b_p);
    {
        dim3 grid(3 * Cc / 128, HW / 128, Bb);
        k_mma_gemm<1, __half><<<grid, 256, gemm_smem>>>(wq_p, 0,
                                                        s_p, (size_t)Cc * HW,
                                                        nullptr, 0, nullptr, 0,
                                                        qkv_p, (size_t)3 * Cc * HW);
    }
    {
        dim3 grid(Bb * NHh, 8);
        k_softmax_lambda<<<grid, 128>>>(qkv_p, lam_p);
    }
    {
        dim3 grid(Ww / 16, Hh / 16, Bb * NHh);
        k_result1<<<grid, 256>>>(qkv_p, lam_p, rel_pos, r1_p);
    }
    {
        dim3 grid(OUTC / 128, HW / 128, Bb);
        k_mma_gemm<2, float><<<grid, 256, gemm_smem>>>(w1_p, 0,
                                                       r1_p, (size_t)Cc * HW,
                                                       w2b_p, (size_t)OUTC * Cc,
                                                       srch_p, (size_t)Cc * HW,
                                                       out, (size_t)OUTC * HW);
    }
}